// round 10
// baseline (speedup 1.0000x reference)
#include <cuda_runtime.h>
#include <cuda_fp16.h>
#include <cstdint>
#include <math.h>

// Problem constants (fixed)
#define OUT_FEATURES 11008
#define IN_FEATURES  4096
#define TOKENS       64
#define BLOCK_SIZE   1024
#define NUM_BLOCKS   (OUT_FEATURES * IN_FEATURES / BLOCK_SIZE)   // 44032
#define W_ELEMS      (OUT_FEATURES * IN_FEATURES)                // 45,088,768
#define KSPLIT       4

// Scratch (device globals; no allocation allowed)
__device__ __half g_W[W_ELEMS];
__device__ __half g_x[TOKENS * IN_FEATURES];
__device__ int    g_qflag;                      // 0=int8, 1=int32, 2=float32
__device__ int    g_ostart[NUM_BLOCKS + 1];     // outlier lower_bound per 1024-block
__device__ float  g_part[KSPLIT][TOKENS * OUT_FEATURES];

// ---------------------------------------------------------------------------
// Kernel 0: detect storage layout of int8_data (harness may upcast).
// ---------------------------------------------------------------------------
__global__ void detect_kernel(const void* __restrict__ qdata)
{
    __shared__ int c_i32, c_f32;
    if (threadIdx.x == 0) { c_i32 = 0; c_f32 = 0; }
    __syncthreads();
    const int t = threadIdx.x;   // 64 threads
    int w = ((const int*)qdata)[t];
    bool vi32 = (w >= -127 && w <= 127);
    float f = __int_as_float(w);
    bool vf32 = (!vi32) && isfinite(f) && fabsf(f) <= 127.0f && f == truncf(f);
    if (vi32) atomicAdd(&c_i32, 1);
    if (vf32) atomicAdd(&c_f32, 1);
    __syncthreads();
    if (t == 0) {
        int flag = 0;
        if (c_i32 >= 32) flag = 1;
        else if (c_f32 >= 32) flag = 2;
        g_qflag = flag;
    }
}

// ---------------------------------------------------------------------------
// Kernel 1: convert x (float32, fp16-exact) -> fp16 scratch.
// ---------------------------------------------------------------------------
__global__ void __launch_bounds__(256) convert_x_kernel(const float* __restrict__ x)
{
    const int i = blockIdx.x * blockDim.x + threadIdx.x;
    float4 f = ((const float4*)x)[i];
    __half2 h0 = __floats2half2_rn(f.x, f.y);
    __half2 h1 = __floats2half2_rn(f.z, f.w);
    uint2 p;
    p.x = *(unsigned*)&h0;
    p.y = *(unsigned*)&h1;
    ((uint2*)g_x)[i] = p;
}

// ---------------------------------------------------------------------------
// Kernel 2: invert fp16_pos -> per-block outlier lower bounds.
// ---------------------------------------------------------------------------
__global__ void __launch_bounds__(256) ostart_kernel(
    const int* __restrict__ fp16_pos, int n_fp16)
{
    const int stride = gridDim.x * blockDim.x;
    for (int i = blockIdx.x * blockDim.x + threadIdx.x; i <= n_fp16; i += stride) {
        int lo = (i == 0) ? 0 : ((fp16_pos[i - 1] >> 10) + 1);
        int hi = (i == n_fp16) ? NUM_BLOCKS : (fp16_pos[i] >> 10);
        for (int b = lo; b <= hi; b++) g_ostart[b] = i;
    }
}

// ---------------------------------------------------------------------------
// Kernel 3: dequantize. One CTA per 1024-elem quant block.
// Closed-form slot rank: with outlier local positions o_j ascending and
// c_j = o_j - j, the flat slot of the k-th non-outlier is
//   lp = k + #{j : c_j <= k}          (independent compares, no fixpoint).
// Output staged in smem (scatter), then ONE coalesced uint4 store per thread.
// ---------------------------------------------------------------------------
__device__ __forceinline__ float4 load_q4(const void* qdata, int flag,
                                          int ci, int n_q)
{
    float4 r;
    if (flag == 2) {
        const float* q = (const float*)qdata;
        if (ci + 4 <= n_q) {
            r = *(const float4*)(q + ci);
        } else {
            r.x = (ci     < n_q) ? q[ci]     : 0.0f;
            r.y = (ci + 1 < n_q) ? q[ci + 1] : 0.0f;
            r.z = (ci + 2 < n_q) ? q[ci + 2] : 0.0f;
            r.w = (ci + 3 < n_q) ? q[ci + 3] : 0.0f;
        }
    } else if (flag == 1) {
        const int* q = (const int*)qdata;
        if (ci + 4 <= n_q) {
            int4 i4 = *(const int4*)(q + ci);
            r.x = (float)i4.x; r.y = (float)i4.y;
            r.z = (float)i4.z; r.w = (float)i4.w;
        } else {
            r.x = (ci     < n_q) ? (float)q[ci]     : 0.0f;
            r.y = (ci + 1 < n_q) ? (float)q[ci + 1] : 0.0f;
            r.z = (ci + 2 < n_q) ? (float)q[ci + 2] : 0.0f;
            r.w = (ci + 3 < n_q) ? (float)q[ci + 3] : 0.0f;
        }
    } else {
        const int8_t* q = (const int8_t*)qdata;
        if (ci + 4 <= n_q) {
            uchar4 u = *(const uchar4*)(q + ci);
            r.x = (float)(int8_t)u.x; r.y = (float)(int8_t)u.y;
            r.z = (float)(int8_t)u.z; r.w = (float)(int8_t)u.w;
        } else {
            r.x = (ci     < n_q) ? (float)q[ci]     : 0.0f;
            r.y = (ci + 1 < n_q) ? (float)q[ci + 1] : 0.0f;
            r.z = (ci + 2 < n_q) ? (float)q[ci + 2] : 0.0f;
            r.w = (ci + 3 < n_q) ? (float)q[ci + 3] : 0.0f;
        }
    }
    return r;
}

__global__ void __launch_bounds__(128) dequant_kernel(
    const void*  __restrict__ qdata,
    const float* __restrict__ fp16_data,
    const float* __restrict__ scales,
    const int*   __restrict__ fp16_pos,
    int n_q)
{
    __shared__ __align__(16) __half s_w[BLOCK_SIZE];  // assembled block
    __shared__ int s_c[1024];                          // c_j = o_j - j

    const int b    = blockIdx.x;
    const int t    = threadIdx.x;
    const int base = b << 10;

    const int o_s  = g_ostart[b];
    const int o_e  = g_ostart[b + 1];
    const int cnt  = o_e - o_s;
    const int cb   = base - o_s;          // compact index of block's first int8
    const int len  = BLOCK_SIZE - cnt;
    const int flag = g_qflag;
    const float sc = scales[b];

    // stage c_j and place outlier values into the smem block directly
    for (int i = t; i < cnt; i += 128) {
        const int o = fp16_pos[o_s + i] - base;   // local outlier position
        s_c[i] = o - i;
        s_w[o] = __float2half_rn(fp16_data[o_s + i]);
    }
    __syncthreads();

    const int a0 = cb & ~3;

    // two vectorized groups (independent loads, full ILP)
    const int ciA = a0 + 4 * t;
    const int ciB = a0 + 512 + 4 * t;
    float4 ra = load_q4(qdata, flag, ciA, n_q);
    float4 rb = load_q4(qdata, flag, ciB, n_q);
    const int kA = ciA - cb;
    const int kB = ciB - cb;

    float v[8] = {ra.x, ra.y, ra.z, ra.w, rb.x, rb.y, rb.z, rb.w};

    // rank: lp_s = k_s + #{c_j <= k_s}; all compares independent
    int lp[8];
    #pragma unroll
    for (int s = 0; s < 8; s++) lp[s] = (s < 4 ? kA : kB) + (s & 3);
    for (int j = 0; j < cnt; j++) {
        const int c = s_c[j];
        #pragma unroll
        for (int s = 0; s < 8; s++) lp[s] += (c <= ((s < 4 ? kA : kB) + (s & 3))) ? 1 : 0;
    }

    #pragma unroll
    for (int s = 0; s < 8; s++) {
        const int k = (s < 4 ? kA : kB) + (s & 3);
        if ((unsigned)k < (unsigned)len)
            s_w[lp[s]] = __float2half_rn(v[s] * sc);
    }

    // tail: compact indices [a0+1024, a0+1032) (head overhang)
    if (t < 2) {
        const int ciT = a0 + 1024 + 4 * t;
        float4 rt = load_q4(qdata, flag, ciT, n_q);
        float vt[4] = {rt.x, rt.y, rt.z, rt.w};
        #pragma unroll
        for (int s = 0; s < 4; s++) {
            const int k = ciT + s - cb;
            if ((unsigned)k < (unsigned)len) {
                int l = k;
                for (int j = 0; j < cnt; j++) l += (s_c[j] <= k) ? 1 : 0;
                s_w[l] = __float2half_rn(vt[s] * sc);
            }
        }
    }
    __syncthreads();

    // single coalesced 16B store per thread: 128 x 16B = 2KB block
    ((uint4*)(g_W + base))[t] = ((const uint4*)s_w)[t];
}

// ---------------------------------------------------------------------------
// Kernel 4: split-K GEMM (proven). grid (172, KSPLIT). 64M x 64N,
// K range 1024, chunks of 64, 3-stage cp.async, mma.sync m16n8k16.
// ---------------------------------------------------------------------------
#define KC      64
#define KPS     (IN_FEATURES / KSPLIT)   // 1024 per split
#define NKC     (KPS / KC)               // 16 chunks
#define STAGES  3
#define SSTRIDE 72
#define STAGE_HALVES (64 * SSTRIDE)      // 4608

__device__ __forceinline__ void cp_async16(void* smem_ptr, const void* gmem_ptr) {
    unsigned saddr = (unsigned)__cvta_generic_to_shared(smem_ptr);
    asm volatile("cp.async.cg.shared.global [%0], [%1], 16;\n" :: "r"(saddr), "l"(gmem_ptr));
}
__device__ __forceinline__ void cp_commit() {
    asm volatile("cp.async.commit_group;\n");
}
template <int N>
__device__ __forceinline__ void cp_wait() {
    asm volatile("cp.async.wait_group %0;\n" :: "n"(N));
}

__global__ void __launch_bounds__(128) gemm_kernel()
{
    extern __shared__ __half smem[];
    __half* As = smem;
    __half* Bs = smem + STAGES * STAGE_HALVES;

    const int n0    = blockIdx.x * 64;
    const int kbase = blockIdx.y * KPS;
    const int t     = threadIdx.x;
    const int warp  = t >> 5;
    const int lane  = t & 31;
    const int g     = lane >> 2;
    const int tid4  = lane & 3;

    const __half* X = g_x;
    const __half* W = g_W;

    auto load_stage = [&](int kc, int st) {
        const int k0 = kbase + kc * KC;
        __half* A = As + st * STAGE_HALVES;
        __half* B = Bs + st * STAGE_HALVES;
        #pragma unroll
        for (int q = 0; q < 4; q++) {
            const int idx = t + q * 128;
            const int row = idx >> 3;
            const int seg = idx & 7;
            cp_async16(A + row * SSTRIDE + seg * 8,
                       X + row * IN_FEATURES + k0 + seg * 8);
            cp_async16(B + row * SSTRIDE + seg * 8,
                       W + (long)(n0 + row) * IN_FEATURES + k0 + seg * 8);
        }
        cp_commit();
    };

    float acc[8][4];
    #pragma unroll
    for (int n = 0; n < 8; n++)
        #pragma unroll
        for (int i = 0; i < 4; i++) acc[n][i] = 0.0f;

    load_stage(0, 0);
    load_stage(1, 1);

    for (int kc = 0; kc < NKC; kc++) {
        const int st = kc % STAGES;
        if (kc == NKC - 1) cp_wait<0>(); else cp_wait<1>();
        __syncthreads();

        if (kc + 2 < NKC) load_stage(kc + 2, (kc + 2) % STAGES);

        const __half* A = As + st * STAGE_HALVES;
        const __half* B = Bs + st * STAGE_HALVES;

        #pragma unroll
        for (int ks = 0; ks < 4; ks++) {
            const int kb = ks * 16;
            unsigned a0, a1, a2, a3;
            {
                const __half* p0 = A + (warp * 16 + g) * SSTRIDE + kb + tid4 * 2;
                const __half* p8 = A + (warp * 16 + g + 8) * SSTRIDE + kb + tid4 * 2;
                a0 = *(const unsigned*)p0;
                a2 = *(const unsigned*)(p0 + 8);
                a1 = *(const unsigned*)p8;
                a3 = *(const unsigned*)(p8 + 8);
            }
            #pragma unroll
            for (int n = 0; n < 8; n++) {
                const __half* pb = B + (n * 8 + g) * SSTRIDE + kb + tid4 * 2;
                unsigned b0 = *(const unsigned*)pb;
                unsigned b1 = *(const unsigned*)(pb + 8);
                asm volatile(
                    "mma.sync.aligned.m16n8k16.row.col.f32.f16.f16.f32 "
                    "{%0,%1,%2,%3}, {%4,%5,%6,%7}, {%8,%9}, {%0,%1,%2,%3};\n"
                    : "+f"(acc[n][0]), "+f"(acc[n][1]), "+f"(acc[n][2]), "+f"(acc[n][3])
                    : "r"(a0), "r"(a1), "r"(a2), "r"(a3), "r"(b0), "r"(b1));
            }
        }
        __syncthreads();
    }

    float* part = g_part[blockIdx.y];
    #pragma unroll
    for (int n = 0; n < 8; n++) {
        const int col = n0 + n * 8 + tid4 * 2;
        const int row0 = warp * 16 + g;
        const int row1 = row0 + 8;
        float2 o0 = make_float2(acc[n][0], acc[n][1]);
        float2 o1 = make_float2(acc[n][2], acc[n][3]);
        *(float2*)(part + row0 * OUT_FEATURES + col) = o0;
        *(float2*)(part + row1 * OUT_FEATURES + col) = o1;
    }
}

// ---------------------------------------------------------------------------
// Kernel 5: reduce split-K partials + bias (fp16-rounding mimic of reference).
// ---------------------------------------------------------------------------
__global__ void __launch_bounds__(256) reduce_kernel(
    const float* __restrict__ bias, float* __restrict__ out)
{
    const int i4 = blockIdx.x * blockDim.x + threadIdx.x;
    const int e0 = i4 * 4;
    const int col = e0 % OUT_FEATURES;

    float4 s  = *(const float4*)&g_part[0][e0];
    float4 s1 = *(const float4*)&g_part[1][e0];
    float4 s2 = *(const float4*)&g_part[2][e0];
    float4 s3 = *(const float4*)&g_part[3][e0];
    s.x += s1.x + s2.x + s3.x;
    s.y += s1.y + s2.y + s3.y;
    s.z += s1.z + s2.z + s3.z;
    s.w += s1.w + s2.w + s3.w;

    float4 bf = *(const float4*)(bias + col);

    float4 o;
    o.x = __half2float(__hadd(__float2half_rn(s.x), __float2half_rn(bf.x)));
    o.y = __half2float(__hadd(__float2half_rn(s.y), __float2half_rn(bf.y)));
    o.z = __half2float(__hadd(__float2half_rn(s.z), __float2half_rn(bf.z)));
    o.w = __half2float(__hadd(__float2half_rn(s.w), __float2half_rn(bf.w)));
    *(float4*)(out + e0) = o;
}

// ---------------------------------------------------------------------------
// Launch. Inputs: x, int8_data, fp16_data, scales, bias, int8_pos, fp16_pos,
// block_idx. int8_pos/block_idx unused by design.
// ---------------------------------------------------------------------------
extern "C" void kernel_launch(void* const* d_in, const int* in_sizes, int n_in,
                              void* d_out, int out_size)
{
    const float* x         = (const float*)d_in[0];
    const void*  int8_data = d_in[1];
    const float* fp16_data = (const float*)d_in[2];
    const float* scales    = (const float*)d_in[3];
    const float* bias      = (const float*)d_in[4];
    const int*   fp16_pos  = (const int*)d_in[6];
    const int    n_fp16    = in_sizes[2];
    const int    n_q       = in_sizes[1];   // element count

    detect_kernel<<<1, 64>>>(int8_data);
    convert_x_kernel<<<TOKENS * IN_FEATURES / (256 * 4), 256>>>(x);
    ostart_kernel<<<256, 256>>>(fp16_pos, n_fp16);
    dequant_kernel<<<NUM_BLOCKS, 128>>>(int8_data, fp16_data, scales, fp16_pos, n_q);

    const int smem_bytes = 2 * STAGES * STAGE_HALVES * (int)sizeof(__half); // 55296
    static bool attr_set = false;
    if (!attr_set) {
        cudaFuncSetAttribute(gemm_kernel,
                             cudaFuncAttributeMaxDynamicSharedMemorySize, smem_bytes);
        attr_set = true;
    }
    gemm_kernel<<<dim3(OUT_FEATURES / 64, KSPLIT), 128, smem_bytes>>>();

    reduce_kernel<<<TOKENS * OUT_FEATURES / (256 * 4), 256>>>(bias, (float*)d_out);
}

// round 12
// speedup vs baseline: 1.1501x; 1.1501x over previous
#include <cuda_runtime.h>
#include <cuda_fp16.h>
#include <cstdint>
#include <math.h>

// Problem constants (fixed)
#define OUT_FEATURES 11008
#define IN_FEATURES  4096
#define TOKENS       64
#define BLOCK_SIZE   1024
#define NUM_BLOCKS   (OUT_FEATURES * IN_FEATURES / BLOCK_SIZE)   // 44032
#define W_ELEMS      (OUT_FEATURES * IN_FEATURES)                // 45,088,768
#define KSPLIT       8

// Scratch (device globals; no allocation allowed)
__device__ __half g_W[W_ELEMS];
__device__ __half g_x[TOKENS * IN_FEATURES];
__device__ int    g_qflag;                      // 0=int8, 1=int32, 2=float32
__device__ int    g_ostart[NUM_BLOCKS + 1];     // outlier lower_bound per 1024-block
__device__ float  g_part[KSPLIT][TOKENS * OUT_FEATURES];

// ---------------------------------------------------------------------------
// Kernel 0: detect storage layout of int8_data (harness may upcast).
// ---------------------------------------------------------------------------
__global__ void detect_kernel(const void* __restrict__ qdata)
{
    __shared__ int c_i32, c_f32;
    if (threadIdx.x == 0) { c_i32 = 0; c_f32 = 0; }
    __syncthreads();
    const int t = threadIdx.x;   // 64 threads
    int w = ((const int*)qdata)[t];
    bool vi32 = (w >= -127 && w <= 127);
    float f = __int_as_float(w);
    bool vf32 = (!vi32) && isfinite(f) && fabsf(f) <= 127.0f && f == truncf(f);
    if (vi32) atomicAdd(&c_i32, 1);
    if (vf32) atomicAdd(&c_f32, 1);
    __syncthreads();
    if (t == 0) {
        int flag = 0;
        if (c_i32 >= 32) flag = 1;
        else if (c_f32 >= 32) flag = 2;
        g_qflag = flag;
    }
}

// ---------------------------------------------------------------------------
// Kernel 1: convert x (float32, fp16-exact) -> fp16 scratch.
// ---------------------------------------------------------------------------
__global__ void __launch_bounds__(256) convert_x_kernel(const float* __restrict__ x)
{
    const int i = blockIdx.x * blockDim.x + threadIdx.x;
    float4 f = ((const float4*)x)[i];
    __half2 h0 = __floats2half2_rn(f.x, f.y);
    __half2 h1 = __floats2half2_rn(f.z, f.w);
    uint2 p;
    p.x = *(unsigned*)&h0;
    p.y = *(unsigned*)&h1;
    ((uint2*)g_x)[i] = p;
}

// ---------------------------------------------------------------------------
// Kernel 2: invert fp16_pos -> per-block outlier lower bounds.
// ---------------------------------------------------------------------------
__global__ void __launch_bounds__(256) ostart_kernel(
    const int* __restrict__ fp16_pos, int n_fp16)
{
    const int stride = gridDim.x * blockDim.x;
    for (int i = blockIdx.x * blockDim.x + threadIdx.x; i <= n_fp16; i += stride) {
        int lo = (i == 0) ? 0 : ((fp16_pos[i - 1] >> 10) + 1);
        int hi = (i == n_fp16) ? NUM_BLOCKS : (fp16_pos[i] >> 10);
        for (int b = lo; b <= hi; b++) g_ostart[b] = i;
    }
}

// ---------------------------------------------------------------------------
// Kernel 3: dequantize (lean). One CTA per 1024-elem quant block.
//   - closed-form slot rank: lp = k + #{j : (o_j - j) <= k}
//   - single uniform dtype branch around two 16B loads
//   - unguarded loads for interior CTAs
//   - direct global half stores; outliers written directly
//   - tail only when head > cnt (the only case it can matter)
// ---------------------------------------------------------------------------
__global__ void __launch_bounds__(128) dequant_kernel(
    const void*  __restrict__ qdata,
    const float* __restrict__ fp16_data,
    const float* __restrict__ scales,
    const int*   __restrict__ fp16_pos,
    int n_q)
{
    __shared__ int s_c[1024];     // c_j = o_j - j (local outlier deltas)

    const int b    = blockIdx.x;
    const int t    = threadIdx.x;
    const int base = b << 10;

    const int o_s  = g_ostart[b];
    const int o_e  = g_ostart[b + 1];
    const int cnt  = o_e - o_s;
    const int cb   = base - o_s;          // compact index of block's first int8
    const int len  = BLOCK_SIZE - cnt;
    const int flag = g_qflag;
    const float sc = scales[b];

    // stage outlier deltas; write outlier values straight to g_W
    for (int i = t; i < cnt; i += 128) {
        const int p = fp16_pos[o_s + i];
        s_c[i] = (p - base) - i;
        g_W[p] = __float2half_rn(fp16_data[o_s + i]);
    }
    __syncthreads();

    const int a0   = cb & ~3;
    const int head = cb - a0;             // 0..3
    const int ciA  = a0 + 4 * t;
    const int ciB  = ciA + 512;
    const int kA   = ciA - cb;
    const int kB   = kA + 512;

    // ---- loads: one uniform dtype branch; unguarded on interior CTAs ----
    float v[8];
    if (flag == 0) {
        const int8_t* q = (const int8_t*)qdata;
        uchar4 ua, ub;
        if (ciB + 4 <= n_q) {
            ua = *(const uchar4*)(q + ciA);
            ub = *(const uchar4*)(q + ciB);
        } else {
            ua.x = (ciA     < n_q) ? (unsigned char)q[ciA]     : 0;
            ua.y = (ciA + 1 < n_q) ? (unsigned char)q[ciA + 1] : 0;
            ua.z = (ciA + 2 < n_q) ? (unsigned char)q[ciA + 2] : 0;
            ua.w = (ciA + 3 < n_q) ? (unsigned char)q[ciA + 3] : 0;
            ub.x = (ciB     < n_q) ? (unsigned char)q[ciB]     : 0;
            ub.y = (ciB + 1 < n_q) ? (unsigned char)q[ciB + 1] : 0;
            ub.z = (ciB + 2 < n_q) ? (unsigned char)q[ciB + 2] : 0;
            ub.w = (ciB + 3 < n_q) ? (unsigned char)q[ciB + 3] : 0;
        }
        v[0] = (float)(int8_t)ua.x; v[1] = (float)(int8_t)ua.y;
        v[2] = (float)(int8_t)ua.z; v[3] = (float)(int8_t)ua.w;
        v[4] = (float)(int8_t)ub.x; v[5] = (float)(int8_t)ub.y;
        v[6] = (float)(int8_t)ub.z; v[7] = (float)(int8_t)ub.w;
    } else {
        const int* q = (const int*)qdata;
        int4 wa, wb;
        if (ciB + 4 <= n_q) {
            wa = *(const int4*)(q + ciA);
            wb = *(const int4*)(q + ciB);
        } else {
            wa.x = (ciA     < n_q) ? q[ciA]     : 0;
            wa.y = (ciA + 1 < n_q) ? q[ciA + 1] : 0;
            wa.z = (ciA + 2 < n_q) ? q[ciA + 2] : 0;
            wa.w = (ciA + 3 < n_q) ? q[ciA + 3] : 0;
            wb.x = (ciB     < n_q) ? q[ciB]     : 0;
            wb.y = (ciB + 1 < n_q) ? q[ciB + 1] : 0;
            wb.z = (ciB + 2 < n_q) ? q[ciB + 2] : 0;
            wb.w = (ciB + 3 < n_q) ? q[ciB + 3] : 0;
        }
        if (flag == 2) {
            v[0] = __int_as_float(wa.x); v[1] = __int_as_float(wa.y);
            v[2] = __int_as_float(wa.z); v[3] = __int_as_float(wa.w);
            v[4] = __int_as_float(wb.x); v[5] = __int_as_float(wb.y);
            v[6] = __int_as_float(wb.z); v[7] = __int_as_float(wb.w);
        } else {
            v[0] = (float)wa.x; v[1] = (float)wa.y;
            v[2] = (float)wa.z; v[3] = (float)wa.w;
            v[4] = (float)wb.x; v[5] = (float)wb.y;
            v[6] = (float)wb.z; v[7] = (float)wb.w;
        }
    }

    // ---- rank: r_s = #{c_j <= k_s}; independent compares ----
    int r[8];
    #pragma unroll
    for (int s = 0; s < 8; s++) r[s] = 0;
    for (int j = 0; j < cnt; j++) {
        const int c = s_c[j];
        r[0] += (c <= kA);     r[1] += (c <= kA + 1);
        r[2] += (c <= kA + 2); r[3] += (c <= kA + 3);
        r[4] += (c <= kB);     r[5] += (c <= kB + 1);
        r[6] += (c <= kB + 2); r[7] += (c <= kB + 3);
    }

    // ---- stores (guard: 0 <= k < len) ----
    #pragma unroll
    for (int s = 0; s < 8; s++) {
        const int k = (s < 4 ? kA : kB - 512 + 512) + (s & 3);   // kA+s or kB+(s-4)
        const int kk = (s < 4) ? (kA + s) : (kB + (s - 4));
        (void)k;
        if ((unsigned)kk < (unsigned)len)
            g_W[base + kk + r[s]] = __float2half_rn(v[s] * sc);
    }

    // ---- tail: only when head > cnt (max 3 elements) ----
    if (head > cnt && t == 0) {
        const int ciT = a0 + 1024;
        for (int s = 0; s < 4; s++) {
            const int k = ciT + s - cb;
            if ((unsigned)k < (unsigned)len) {
                float tv;
                if (flag == 0)      tv = (float)((const int8_t*)qdata)[ciT + s];
                else if (flag == 1) tv = (float)((const int*)qdata)[ciT + s];
                else                tv = ((const float*)qdata)[ciT + s];
                int l = k;
                for (int j = 0; j < cnt; j++) l += (s_c[j] <= k) ? 1 : 0;
                g_W[base + l] = __float2half_rn(tv * sc);
            }
        }
    }
}

// ---------------------------------------------------------------------------
// Kernel 4: split-K GEMM (proven). grid (172, KSPLIT). 64M x 64N,
// K range 512, chunks of 64, 3-stage cp.async, mma.sync m16n8k16.
// ---------------------------------------------------------------------------
#define KC      64
#define KPS     (IN_FEATURES / KSPLIT)   // 512 per split
#define NKC     (KPS / KC)               // 8 chunks
#define STAGES  3
#define SSTRIDE 72
#define STAGE_HALVES (64 * SSTRIDE)      // 4608

__device__ __forceinline__ void cp_async16(void* smem_ptr, const void* gmem_ptr) {
    unsigned saddr = (unsigned)__cvta_generic_to_shared(smem_ptr);
    asm volatile("cp.async.cg.shared.global [%0], [%1], 16;\n" :: "r"(saddr), "l"(gmem_ptr));
}
__device__ __forceinline__ void cp_commit() {
    asm volatile("cp.async.commit_group;\n");
}
template <int N>
__device__ __forceinline__ void cp_wait() {
    asm volatile("cp.async.wait_group %0;\n" :: "n"(N));
}

__global__ void __launch_bounds__(128) gemm_kernel()
{
    extern __shared__ __half smem[];
    __half* As = smem;
    __half* Bs = smem + STAGES * STAGE_HALVES;

    const int n0    = blockIdx.x * 64;
    const int kbase = blockIdx.y * KPS;
    const int t     = threadIdx.x;
    const int warp  = t >> 5;
    const int lane  = t & 31;
    const int g     = lane >> 2;
    const int tid4  = lane & 3;

    const __half* X = g_x;
    const __half* W = g_W;

    auto load_stage = [&](int kc, int st) {
        const int k0 = kbase + kc * KC;
        __half* A = As + st * STAGE_HALVES;
        __half* B = Bs + st * STAGE_HALVES;
        #pragma unroll
        for (int q = 0; q < 4; q++) {
            const int idx = t + q * 128;
            const int row = idx >> 3;
            const int seg = idx & 7;
            cp_async16(A + row * SSTRIDE + seg * 8,
                       X + row * IN_FEATURES + k0 + seg * 8);
            cp_async16(B + row * SSTRIDE + seg * 8,
                       W + (long)(n0 + row) * IN_FEATURES + k0 + seg * 8);
        }
        cp_commit();
    };

    float acc[8][4];
    #pragma unroll
    for (int n = 0; n < 8; n++)
        #pragma unroll
        for (int i = 0; i < 4; i++) acc[n][i] = 0.0f;

    load_stage(0, 0);
    load_stage(1, 1);

    for (int kc = 0; kc < NKC; kc++) {
        const int st = kc % STAGES;
        if (kc == NKC - 1) cp_wait<0>(); else cp_wait<1>();
        __syncthreads();

        if (kc + 2 < NKC) load_stage(kc + 2, (kc + 2) % STAGES);

        const __half* A = As + st * STAGE_HALVES;
        const __half* B = Bs + st * STAGE_HALVES;

        #pragma unroll
        for (int ks = 0; ks < 4; ks++) {
            const int kb = ks * 16;
            unsigned a0, a1, a2, a3;
            {
                const __half* p0 = A + (warp * 16 + g) * SSTRIDE + kb + tid4 * 2;
                const __half* p8 = A + (warp * 16 + g + 8) * SSTRIDE + kb + tid4 * 2;
                a0 = *(const unsigned*)p0;
                a2 = *(const unsigned*)(p0 + 8);
                a1 = *(const unsigned*)p8;
                a3 = *(const unsigned*)(p8 + 8);
            }
            #pragma unroll
            for (int n = 0; n < 8; n++) {
                const __half* pb = B + (n * 8 + g) * SSTRIDE + kb + tid4 * 2;
                unsigned b0 = *(const unsigned*)pb;
                unsigned b1 = *(const unsigned*)(pb + 8);
                asm volatile(
                    "mma.sync.aligned.m16n8k16.row.col.f32.f16.f16.f32 "
                    "{%0,%1,%2,%3}, {%4,%5,%6,%7}, {%8,%9}, {%0,%1,%2,%3};\n"
                    : "+f"(acc[n][0]), "+f"(acc[n][1]), "+f"(acc[n][2]), "+f"(acc[n][3])
                    : "r"(a0), "r"(a1), "r"(a2), "r"(a3), "r"(b0), "r"(b1));
            }
        }
        __syncthreads();
    }

    float* part = g_part[blockIdx.y];
    #pragma unroll
    for (int n = 0; n < 8; n++) {
        const int col = n0 + n * 8 + tid4 * 2;
        const int row0 = warp * 16 + g;
        const int row1 = row0 + 8;
        float2 o0 = make_float2(acc[n][0], acc[n][1]);
        float2 o1 = make_float2(acc[n][2], acc[n][3]);
        *(float2*)(part + row0 * OUT_FEATURES + col) = o0;
        *(float2*)(part + row1 * OUT_FEATURES + col) = o1;
    }
}

// ---------------------------------------------------------------------------
// Kernel 5: reduce split-K partials + bias (fp16-rounding mimic of reference).
// ---------------------------------------------------------------------------
__global__ void __launch_bounds__(256) reduce_kernel(
    const float* __restrict__ bias, float* __restrict__ out)
{
    const int i4 = blockIdx.x * blockDim.x + threadIdx.x;
    const int e0 = i4 * 4;
    const int col = e0 % OUT_FEATURES;

    float4 s = *(const float4*)&g_part[0][e0];
    #pragma unroll
    for (int z = 1; z < KSPLIT; z++) {
        float4 p = *(const float4*)&g_part[z][e0];
        s.x += p.x; s.y += p.y; s.z += p.z; s.w += p.w;
    }

    float4 bf = *(const float4*)(bias + col);

    float4 o;
    o.x = __half2float(__hadd(__float2half_rn(s.x), __float2half_rn(bf.x)));
    o.y = __half2float(__hadd(__float2half_rn(s.y), __float2half_rn(bf.y)));
    o.z = __half2float(__hadd(__float2half_rn(s.z), __float2half_rn(bf.z)));
    o.w = __half2float(__hadd(__float2half_rn(s.w), __float2half_rn(bf.w)));
    *(float4*)(out + e0) = o;
}

// ---------------------------------------------------------------------------
// Launch. Inputs: x, int8_data, fp16_data, scales, bias, int8_pos, fp16_pos,
// block_idx. int8_pos/block_idx unused by design.
// ---------------------------------------------------------------------------
extern "C" void kernel_launch(void* const* d_in, const int* in_sizes, int n_in,
                              void* d_out, int out_size)
{
    const float* x         = (const float*)d_in[0];
    const void*  int8_data = d_in[1];
    const float* fp16_data = (const float*)d_in[2];
    const float* scales    = (const float*)d_in[3];
    const float* bias      = (const float*)d_in[4];
    const int*   fp16_pos  = (const int*)d_in[6];
    const int    n_fp16    = in_sizes[2];
    const int    n_q       = in_sizes[1];   // element count

    detect_kernel<<<1, 64>>>(int8_data);
    convert_x_kernel<<<TOKENS * IN_FEATURES / (256 * 4), 256>>>(x);
    ostart_kernel<<<256, 256>>>(fp16_pos, n_fp16);
    dequant_kernel<<<NUM_BLOCKS, 128>>>(int8_data, fp16_data, scales, fp16_pos, n_q);

    const int smem_bytes = 2 * STAGES * STAGE_HALVES * (int)sizeof(__half); // 55296
    static bool attr_set = false;
    if (!attr_set) {
        cudaFuncSetAttribute(gemm_kernel,
                             cudaFuncAttributeMaxDynamicSharedMemorySize, smem_bytes);
        attr_set = true;
    }
    gemm_kernel<<<dim3(OUT_FEATURES / 64, KSPLIT), 128, smem_bytes>>>();

    reduce_kernel<<<TOKENS * OUT_FEATURES / (256 * 4), 256>>>(bias, (float*)d_out);
}